// round 14
// baseline (speedup 1.0000x reference)
#include <cuda_runtime.h>

// DWT Haar L1 loss, single fused kernel:
//   loss = (2/N) * sum over 2x2 blocks of |a+b+c+d|+|a+b-c-d|+|a-b+c-d|+|a-b-c+d|
// with (a,b,c,d) = pred - target at the 4 block positions.
//
// Mainloop: grid-stride unrolled x2 across the stride — 8 independent
// fully-coalesced LDG.E.128 in flight per thread, every warp transaction a
// dense 512B access. 4736 CTAs (4 waves) = fine scheduling quanta so
// GigaThread load-balances fast/slow SMs and the tail wave is short.
// Final reduction fused via last-block-done ticket (single launch).

#define NBLOCKS 4736   // 148 SMs x 32 -> 4 waves of 8 CTAs/SM

__device__ float        g_partials[NBLOCKS];
__device__ unsigned int g_ticket = 0;   // reset by last block each launch

__device__ __forceinline__ float haar2(float4 p0, float4 p1, float4 t0, float4 t1)
{
    // Two 2x2 Haar blocks from one float4-pair of rows.
    float a = p0.x - t0.x;
    float b = p0.y - t0.y;
    float c = p1.x - t1.x;
    float d = p1.y - t1.y;
    float s0 = a + b, s1 = c + d, d0 = a - b, d1 = c - d;
    float r = fabsf(s0 + s1) + fabsf(s0 - s1) + fabsf(d0 + d1) + fabsf(d0 - d1);
    a = p0.z - t0.z;
    b = p0.w - t0.w;
    c = p1.z - t1.z;
    d = p1.w - t1.w;
    s0 = a + b; s1 = c + d; d0 = a - b; d1 = c - d;
    r += fabsf(s0 + s1) + fabsf(s0 - s1) + fabsf(d0 + d1) + fabsf(d0 - d1);
    return r;
}

__global__ void __launch_bounds__(256)
dwt_loss_kernel(const float* __restrict__ pred,
                const float* __restrict__ target,
                float* __restrict__ out,
                int nwork, float scale)
{
    float acc = 0.0f;
    const int stride = gridDim.x * blockDim.x;
    int i = blockIdx.x * blockDim.x + threadIdx.x;

    // Unrolled x2: items i and i+stride per iteration, both coalesced.
    for (; i + stride < nwork; i += 2 * stride) {
        int j = i + stride;

        int pair0 = i >> 7;
        int xv0   = i & 127;
        size_t b0 = (size_t)pair0 * 1024 + (size_t)xv0 * 4;
        int pair1 = j >> 7;
        int xv1   = j & 127;
        size_t b1 = (size_t)pair1 * 1024 + (size_t)xv1 * 4;

        float4 p0a = *reinterpret_cast<const float4*>(pred   + b0);
        float4 p1a = *reinterpret_cast<const float4*>(pred   + b0 + 512);
        float4 t0a = *reinterpret_cast<const float4*>(target + b0);
        float4 t1a = *reinterpret_cast<const float4*>(target + b0 + 512);
        float4 p0b = *reinterpret_cast<const float4*>(pred   + b1);
        float4 p1b = *reinterpret_cast<const float4*>(pred   + b1 + 512);
        float4 t0b = *reinterpret_cast<const float4*>(target + b1);
        float4 t1b = *reinterpret_cast<const float4*>(target + b1 + 512);

        acc += haar2(p0a, p1a, t0a, t1a);
        acc += haar2(p0b, p1b, t0b, t1b);
    }
    // Tail: at most one remaining item per thread.
    if (i < nwork) {
        int pair = i >> 7;
        int xv   = i & 127;
        size_t b = (size_t)pair * 1024 + (size_t)xv * 4;
        float4 p0 = *reinterpret_cast<const float4*>(pred   + b);
        float4 p1 = *reinterpret_cast<const float4*>(pred   + b + 512);
        float4 t0 = *reinterpret_cast<const float4*>(target + b);
        float4 t1 = *reinterpret_cast<const float4*>(target + b + 512);
        acc += haar2(p0, p1, t0, t1);
    }

    // ---- intra-block reduction ----
    #pragma unroll
    for (int o = 16; o > 0; o >>= 1)
        acc += __shfl_down_sync(0xffffffffu, acc, o);

    __shared__ float smem[8];
    __shared__ bool  s_last;
    int lane = threadIdx.x & 31;
    int wid  = threadIdx.x >> 5;
    if (lane == 0) smem[wid] = acc;
    __syncthreads();

    if (wid == 0) {
        acc = (lane < 8) ? smem[lane] : 0.0f;
        #pragma unroll
        for (int o = 4; o > 0; o >>= 1)
            acc += __shfl_down_sync(0xffffffffu, acc, o);
        if (lane == 0) {
            g_partials[blockIdx.x] = acc;
            __threadfence();
            unsigned int t = atomicAdd(&g_ticket, 1u);
            s_last = (t == (unsigned int)(gridDim.x - 1));
        }
    }
    __syncthreads();

    // ---- last block to finish reduces all partials ----
    if (s_last) {
        __threadfence();
        float v = 0.0f;
        for (int k = threadIdx.x; k < NBLOCKS; k += 256)
            v += g_partials[k];
        #pragma unroll
        for (int o = 16; o > 0; o >>= 1)
            v += __shfl_down_sync(0xffffffffu, v, o);
        if (lane == 0) smem[wid] = v;
        __syncthreads();
        if (wid == 0) {
            v = (lane < 8) ? smem[lane] : 0.0f;
            #pragma unroll
            for (int o = 4; o > 0; o >>= 1)
                v += __shfl_down_sync(0xffffffffu, v, o);
            if (lane == 0) {
                out[0] = v * scale;
                g_ticket = 0;   // reset for next graph replay
            }
        }
    }
}

extern "C" void kernel_launch(void* const* d_in, const int* in_sizes, int n_in,
                              void* d_out, int out_size)
{
    const float* pred   = (const float*)d_in[0];
    const float* target = (const float*)d_in[1];
    float* out = (float*)d_out;

    const int total = in_sizes[0];          // 32*3*512*512 = 25,165,824
    const int nwork = total / 8;            // 8 elems of each tensor per item
    const float scale = 2.0f / (float)total;

    dwt_loss_kernel<<<NBLOCKS, 256>>>(pred, target, out, nwork, scale);
}

// round 15
// speedup vs baseline: 1.1096x; 1.1096x over previous
#include <cuda_runtime.h>

// DWT Haar L1 loss, single fused kernel:
//   loss = (2/N) * sum over 2x2 blocks of |a+b+c+d|+|a+b-c-d|+|a-b+c-d|+|a-b-c+d|
// with (a,b,c,d) = pred - target at the 4 block positions.
//
// Configuration with the best evidence across 7 measured rounds:
//  - 2368 CTAs x 256 (2 waves: dynamic balancing, minimal wave transitions)
//  - grid-stride mainloop unrolled x2 across stride: 8 independent
//    fully-coalesced LDG.E.128 in flight per thread, every warp transaction
//    a dense 512B access
//  - final reduction fused via last-block-done ticket (single launch)
// Runs at 97-98% of session-achievable HBM bandwidth; all compute pipes idle.

#define NBLOCKS 2368   // 148 SMs x 16

__device__ float        g_partials[NBLOCKS];
__device__ unsigned int g_ticket = 0;   // reset by last block each launch

__device__ __forceinline__ float haar2(float4 p0, float4 p1, float4 t0, float4 t1)
{
    // Two 2x2 Haar blocks from one float4-pair of rows.
    float a = p0.x - t0.x;
    float b = p0.y - t0.y;
    float c = p1.x - t1.x;
    float d = p1.y - t1.y;
    float s0 = a + b, s1 = c + d, d0 = a - b, d1 = c - d;
    float r = fabsf(s0 + s1) + fabsf(s0 - s1) + fabsf(d0 + d1) + fabsf(d0 - d1);
    a = p0.z - t0.z;
    b = p0.w - t0.w;
    c = p1.z - t1.z;
    d = p1.w - t1.w;
    s0 = a + b; s1 = c + d; d0 = a - b; d1 = c - d;
    r += fabsf(s0 + s1) + fabsf(s0 - s1) + fabsf(d0 + d1) + fabsf(d0 - d1);
    return r;
}

__global__ void __launch_bounds__(256)
dwt_loss_kernel(const float* __restrict__ pred,
                const float* __restrict__ target,
                float* __restrict__ out,
                int nwork, float scale)
{
    float acc = 0.0f;
    const int stride = gridDim.x * blockDim.x;
    int i = blockIdx.x * blockDim.x + threadIdx.x;

    // Unrolled x2: items i and i+stride per iteration, both coalesced.
    for (; i + stride < nwork; i += 2 * stride) {
        int j = i + stride;

        int pair0 = i >> 7;
        int xv0   = i & 127;
        size_t b0 = (size_t)pair0 * 1024 + (size_t)xv0 * 4;
        int pair1 = j >> 7;
        int xv1   = j & 127;
        size_t b1 = (size_t)pair1 * 1024 + (size_t)xv1 * 4;

        float4 p0a = *reinterpret_cast<const float4*>(pred   + b0);
        float4 p1a = *reinterpret_cast<const float4*>(pred   + b0 + 512);
        float4 t0a = *reinterpret_cast<const float4*>(target + b0);
        float4 t1a = *reinterpret_cast<const float4*>(target + b0 + 512);
        float4 p0b = *reinterpret_cast<const float4*>(pred   + b1);
        float4 p1b = *reinterpret_cast<const float4*>(pred   + b1 + 512);
        float4 t0b = *reinterpret_cast<const float4*>(target + b1);
        float4 t1b = *reinterpret_cast<const float4*>(target + b1 + 512);

        acc += haar2(p0a, p1a, t0a, t1a);
        acc += haar2(p0b, p1b, t0b, t1b);
    }
    // Tail: at most one remaining item per thread.
    if (i < nwork) {
        int pair = i >> 7;
        int xv   = i & 127;
        size_t b = (size_t)pair * 1024 + (size_t)xv * 4;
        float4 p0 = *reinterpret_cast<const float4*>(pred   + b);
        float4 p1 = *reinterpret_cast<const float4*>(pred   + b + 512);
        float4 t0 = *reinterpret_cast<const float4*>(target + b);
        float4 t1 = *reinterpret_cast<const float4*>(target + b + 512);
        acc += haar2(p0, p1, t0, t1);
    }

    // ---- intra-block reduction ----
    #pragma unroll
    for (int o = 16; o > 0; o >>= 1)
        acc += __shfl_down_sync(0xffffffffu, acc, o);

    __shared__ float smem[8];
    __shared__ bool  s_last;
    int lane = threadIdx.x & 31;
    int wid  = threadIdx.x >> 5;
    if (lane == 0) smem[wid] = acc;
    __syncthreads();

    if (wid == 0) {
        acc = (lane < 8) ? smem[lane] : 0.0f;
        #pragma unroll
        for (int o = 4; o > 0; o >>= 1)
            acc += __shfl_down_sync(0xffffffffu, acc, o);
        if (lane == 0) {
            g_partials[blockIdx.x] = acc;
            __threadfence();
            unsigned int t = atomicAdd(&g_ticket, 1u);
            s_last = (t == (unsigned int)(gridDim.x - 1));
        }
    }
    __syncthreads();

    // ---- last block to finish reduces all partials ----
    if (s_last) {
        __threadfence();
        float v = 0.0f;
        for (int k = threadIdx.x; k < NBLOCKS; k += 256)
            v += g_partials[k];
        #pragma unroll
        for (int o = 16; o > 0; o >>= 1)
            v += __shfl_down_sync(0xffffffffu, v, o);
        if (lane == 0) smem[wid] = v;
        __syncthreads();
        if (wid == 0) {
            v = (lane < 8) ? smem[lane] : 0.0f;
            #pragma unroll
            for (int o = 4; o > 0; o >>= 1)
                v += __shfl_down_sync(0xffffffffu, v, o);
            if (lane == 0) {
                out[0] = v * scale;
                g_ticket = 0;   // reset for next graph replay
            }
        }
    }
}

extern "C" void kernel_launch(void* const* d_in, const int* in_sizes, int n_in,
                              void* d_out, int out_size)
{
    const float* pred   = (const float*)d_in[0];
    const float* target = (const float*)d_in[1];
    float* out = (float*)d_out;

    const int total = in_sizes[0];          // 32*3*512*512 = 25,165,824
    const int nwork = total / 8;            // 8 elems of each tensor per item
    const float scale = 2.0f / (float)total;

    dwt_loss_kernel<<<NBLOCKS, 256>>>(pred, target, out, nwork, scale);
}